// round 10
// baseline (speedup 1.0000x reference)
#include <cuda_runtime.h>
#include <cuda_bf16.h>
#include <float.h>
#include <limits.h>

#define FULL 0xFFFFFFFFu

static constexpr int B = 4;
static constexpr int N = 8192;
static constexpr int M = 2048;
static constexpr int F = 256;
static constexpr int K = 16;
static constexpr int OUTC = 3 + F;     // 259
static constexpr int HB = 256;         // point x-buckets
static constexpr int QB = 128;         // query x-buckets
static constexpr int NG = N / 32;      // 256 groups of 32 sorted points
static constexpr float SLACK = 1e-3f;  // prune slack >> fp32 rounding of d2

static constexpr int KNNB = (B * M) / 16;              // 512 knn blocks
static constexpr int TRB  = B * (F / 32) * (N / 128);  // 2048 transpose tiles

// ---------------- device scratch (no allocation allowed) ----------------
__device__ float4 g_spts[B * N];          // sorted by x: (x,y,z, p2) p2=R1 fmaf chain
__device__ int    g_sidx[B * N];          // sorted pos -> original point index
__device__ float  g_gmin[B * NG];         // per-32-group exact x bounds
__device__ float  g_gmax[B * NG];
__device__ float  g_emaxL[B * NG];        // cummax of g_gmax from left
__device__ float  g_eminR[B * NG];        // cummin of g_gmin from right
__device__ int    g_qord[B * M];          // sorted query order -> original m
__device__ int    g_hist[B * HB];
__device__ int    g_off [B * HB];         // excl offsets; ends as end-offsets
__device__ int    g_qhist[B * QB];
__device__ int    g_qoff [B * QB];
__device__ float  g_featT[(size_t)B * N * F];  // transposed features (B,N,F)
__device__ int    g_idx[B * M * K];
__device__ float  g_w  [B * M * K];

__device__ __forceinline__ int clampi(int v, int lo, int hi) {
    return v < lo ? lo : (v > hi ? hi : v);
}

// ---------------- P0: zero histograms --------------------------------------
__global__ void zero_kernel() {
    int tid = threadIdx.x;
    for (int i = tid; i < B * HB; i += 512) g_hist[i] = 0;
    for (int i = tid; i < B * QB; i += 512) g_qhist[i] = 0;
}

// ---------------- P1: histogram points + queries by x ----------------------
__global__ __launch_bounds__(512) void hist_kernel(
    const float* __restrict__ pc, const float* __restrict__ qc)
{
    int g = blockIdx.x * 512 + threadIdx.x;
    if (g < B * N) {
        int b = g >> 13, n = g & (N - 1);
        float x = pc[(size_t)b * 3 * N + n];
        int bp = clampi((int)((x + 4.0f) * 32.0f), 0, HB - 1);
        atomicAdd(&g_hist[b * HB + bp], 1);
    } else {
        int q = g - B * N;
        int b = q >> 11, m = q & (M - 1);
        float x = qc[(size_t)b * 3 * M + m];
        int bq = clampi((int)((x + 4.0f) * 16.0f), 0, QB - 1);
        atomicAdd(&g_qhist[b * QB + bq], 1);
    }
}

// ---------------- P2: exclusive scans (1 block, per-batch) -----------------
__global__ void scan_kernel() {
    int lane = threadIdx.x & 31;
    int w    = threadIdx.x >> 5;
    if (w < 4) {
        int b = w;
        int loc[8], tot = 0;
        #pragma unroll
        for (int i = 0; i < 8; ++i) { loc[i] = tot; tot += g_hist[b * HB + lane * 8 + i]; }
        int inc = tot;
        #pragma unroll
        for (int o = 1; o < 32; o <<= 1) {
            int t = __shfl_up_sync(FULL, inc, o);
            if (lane >= o) inc += t;
        }
        int ex = inc - tot;
        #pragma unroll
        for (int i = 0; i < 8; ++i) g_off[b * HB + lane * 8 + i] = ex + loc[i];
    } else if (w < 8) {
        int b = w - 4;
        int loc[4], tot = 0;
        #pragma unroll
        for (int i = 0; i < 4; ++i) { loc[i] = tot; tot += g_qhist[b * QB + lane * 4 + i]; }
        int inc = tot;
        #pragma unroll
        for (int o = 1; o < 32; o <<= 1) {
            int t = __shfl_up_sync(FULL, inc, o);
            if (lane >= o) inc += t;
        }
        int ex = inc - tot;
        #pragma unroll
        for (int i = 0; i < 4; ++i) g_qoff[b * QB + lane * 4 + i] = ex + loc[i];
    }
}

// ---------------- P3: scatter into sorted-by-x order -----------------------
__global__ __launch_bounds__(512) void scatter_kernel(
    const float* __restrict__ pc, const float* __restrict__ qc)
{
    int g = blockIdx.x * 512 + threadIdx.x;
    if (g < B * N) {
        int b = g >> 13, n = g & (N - 1);
        const float* pcb = pc + (size_t)b * 3 * N;
        float x = pcb[n], y = pcb[N + n], z = pcb[2 * N + n];
        int bp = clampi((int)((x + 4.0f) * 32.0f), 0, HB - 1);
        int pos = atomicAdd(&g_off[b * HB + bp], 1);
        // p2 with EXACT R1 fmaf chain (key bits must match R1's)
        g_spts[b * N + pos] = make_float4(x, y, z, fmaf(x, x, fmaf(y, y, z * z)));
        g_sidx[b * N + pos] = n;
    } else {
        int q = g - B * N;
        int b = q >> 11, m = q & (M - 1);
        float x = qc[(size_t)b * 3 * M + m];
        int bq = clampi((int)((x + 4.0f) * 16.0f), 0, QB - 1);
        int pos = atomicAdd(&g_qoff[b * QB + bq], 1);
        g_qord[b * M + pos] = m;
    }
}

// ---------------- P4: exact per-group x bounds -----------------------------
__global__ __launch_bounds__(512) void bounds_kernel() {
    int g = blockIdx.x * 512 + threadIdx.x;
    if (g >= B * NG) return;
    int b = g >> 8, gl = g & (NG - 1);
    float mn = FLT_MAX, mx = -FLT_MAX;
    #pragma unroll 8
    for (int i = 0; i < 32; ++i) {
        float x = g_spts[b * N + gl * 32 + i].x;
        mn = fminf(mn, x);
        mx = fmaxf(mx, x);
    }
    g_gmin[g] = mn;
    g_gmax[g] = mx;
}

// ---------------- P5: monotone envelopes -----------------------------------
__global__ void envelope_kernel() {
    int lane = threadIdx.x & 31;
    int w    = threadIdx.x >> 5;
    if (w < 4) {
        int b = w;
        float carry = -FLT_MAX;
        for (int c = 0; c < NG / 32; ++c) {
            float v = g_gmax[b * NG + c * 32 + lane];
            #pragma unroll
            for (int o = 1; o < 32; o <<= 1) {
                float t = __shfl_up_sync(FULL, v, o);
                if (lane >= o) v = fmaxf(v, t);
            }
            v = fmaxf(v, carry);
            g_emaxL[b * NG + c * 32 + lane] = v;
            carry = __shfl_sync(FULL, v, 31);
        }
    } else if (w < 8) {
        int b = w - 4;
        float carry = FLT_MAX;
        for (int c = 0; c < NG / 32; ++c) {
            int ridx = NG - 1 - (c * 32 + lane);
            float v = g_gmin[b * NG + ridx];
            #pragma unroll
            for (int o = 1; o < 32; o <<= 1) {
                float t = __shfl_up_sync(FULL, v, o);
                if (lane >= o) v = fminf(v, t);
            }
            v = fminf(v, carry);
            g_eminR[b * NG + ridx] = v;
            carry = __shfl_sync(FULL, v, 31);
        }
    }
}

// ---------------- KNN (ring + rescan, R1 key + index tie-break) + transpose -
__global__ __launch_bounds__(512) void knn_tr_kernel(
    const float* __restrict__ qc,
    const float* __restrict__ temperature,
    const float* __restrict__ feat,
    float* __restrict__ out)
{
    __shared__ float tile[32][129];

    if (blockIdx.x < KNNB) {
        const int lane = threadIdx.x & 31;
        const int wid  = threadIdx.x >> 5;
        const int b    = blockIdx.x >> 7;
        const int qp   = ((blockIdx.x & 127) << 4) + wid;   // sorted query pos
        const int m    = g_qord[b * M + qp];

        const float qx = qc[((size_t)b * 3 + 0) * M + m];
        const float qy = qc[((size_t)b * 3 + 1) * M + m];
        const float qz = qc[((size_t)b * 3 + 2) * M + m];
        const float q2 = fmaf(qx, qx, fmaf(qy, qy, qz * qz));
        const float ax = -2.0f * qx, ay = -2.0f * qy, az = -2.0f * qz;

        const float4* __restrict__ P   = g_spts + b * N;
        const int*    __restrict__ SI  = g_sidx + b * N;
        const float*  __restrict__ EL  = g_emaxL + b * NG;
        const float*  __restrict__ ER  = g_eminR + b * NG;
        const float*  __restrict__ GMN = g_gmin + b * NG;
        const float*  __restrict__ GMX = g_gmax + b * NG;

        int bq = clampi((int)((qx + 4.0f) * 32.0f), 0, HB - 1);
        int g0 = clampi(g_off[b * HB + bq] >> 5, 0, NG - 1);

        // warp-distributed sorted list ordered by (key, orig index):
        // lane i = i-th best. Tie-break = lowest original index (== top_k).
        float kd    = FLT_MAX;
        int   kOrig = INT_MAX;
        int   kpos  = 0;
        float thr     = FLT_MAX;   // 16th-best key
        int   thrOrig = INT_MAX;   // its original index

        auto score = [&](int g) {
            float4 p = P[g * 32 + lane];
            int   orig = SI[g * 32 + lane];
            // EXACT R1 key chain: s = |p|^2 - 2 q.p  (no q2 term)
            float s = fmaf(ax, p.x, p.w);
            s = fmaf(ay, p.y, s);
            s = fmaf(az, p.z, s);
            bool accept = (s < thr) || (s == thr && orig < thrOrig);
            unsigned mask = __ballot_sync(FULL, accept);
            if (mask) {
                int base = g * 32;
                do {
                    int src = __ffs(mask) - 1; mask &= mask - 1;
                    float cd = __shfl_sync(FULL, s, src);
                    int   co = __shfl_sync(FULL, orig, src);
                    // existing entry ranks ahead iff (kd,kOrig) < (cd,co)
                    bool better = (kd < cd) || (kd == cd && kOrig < co);
                    int pos = __popc(__ballot_sync(FULL, better));
                    float ud = __shfl_up_sync(FULL, kd, 1);
                    int   uo = __shfl_up_sync(FULL, kOrig, 1);
                    int   up = __shfl_up_sync(FULL, kpos, 1);
                    if (lane >= pos) {
                        kd    = (lane == pos) ? cd : ud;
                        kOrig = (lane == pos) ? co : uo;
                        kpos  = (lane == pos) ? (base + src) : up;
                    }
                } while (mask);
                thr     = __shfl_sync(FULL, kd, 15);
                thrOrig = __shfl_sync(FULL, kOrig, 15);
            }
        };

        // ring expansion; prune in d2-space: d2 = s + q2 (+ SLACK margin).
        // thr==FLT_MAX early -> thr+q2+SLACK = inf, never prunes prematurely.
        int lo = g0, hi = g0 + 1;
        int loStop = -1, hiStop = NG;
        while (lo >= 0 || hi < NG) {
            float bound = thr + q2 + SLACK;
            if (lo >= 0) {
                float gap = qx - EL[lo];
                if (gap > 0.0f && gap * gap >= bound) { loStop = lo; lo = -1; }
                else { score(lo); --lo; }
            }
            if (hi < NG) {
                float gap = ER[hi] - qx;
                if (gap > 0.0f && gap * gap >= bound) { hiStop = hi; hi = NG; }
                else { score(hi); ++hi; }
            }
        }

        // exact rescan of unvisited groups (per-group bounds + slack)
        for (int g = loStop; g >= 0; --g) {
            float bound = thr + q2 + SLACK;
            float gapL = qx - GMX[g];
            float gapR = GMN[g] - qx;
            bool skip = (gapL > 0.0f && gapL * gapL >= bound) ||
                        (gapR > 0.0f && gapR * gapR >= bound);
            if (!skip) score(g);
        }
        for (int g = hiStop; g < NG; ++g) {
            float bound = thr + q2 + SLACK;
            float gapL = qx - GMX[g];
            float gapR = GMN[g] - qx;
            bool skip = (gapL > 0.0f && gapL * gapL >= bound) ||
                        (gapR > 0.0f && gapR * gapR >= bound);
            if (!skip) score(g);
        }

        // softmax over the 16 best keys (shift-invariant in s) — R1 formula
        float tv = *temperature;
        float inv_sigma = 1.0f / fmaxf(tv * tv, 1e-4f);
        float s0 = __shfl_sync(FULL, kd, 0);
        float ev = (lane < K) ? __expf((s0 - kd) * inv_sigma) : 0.0f;
        float sum = ev;
        #pragma unroll
        for (int o = 16; o; o >>= 1) sum += __shfl_xor_sync(FULL, sum, o);
        float w = ev / sum;

        float4 pk = P[kpos];
        float sx = w * pk.x, sy = w * pk.y, sz = w * pk.z;
        #pragma unroll
        for (int o = 16; o; o >>= 1) {
            sx += __shfl_xor_sync(FULL, sx, o);
            sy += __shfl_xor_sync(FULL, sy, o);
            sz += __shfl_xor_sync(FULL, sz, o);
        }
        if (lane == 0) {
            out[((size_t)b * OUTC + 0) * M + m] = sx;
            out[((size_t)b * OUTC + 1) * M + m] = sy;
            out[((size_t)b * OUTC + 2) * M + m] = sz;
        }
        if (lane < K) {
            size_t gq = (size_t)b * M + m;
            g_idx[gq * K + lane] = kOrig;
            g_w[gq * K + lane]   = w;
        }
    } else {
        // ---------------- transpose (R9-proven geometry) -------------------
        int t  = blockIdx.x - KNNB;
        int b  = t >> 9;
        int r  = t & 511;
        int fb = r >> 6;
        int nb = r & 63;

        int tx = threadIdx.x & 127;
        int ty = threadIdx.x >> 7;
        const float* src = feat + ((size_t)b * F + fb * 32) * N + nb * 128;
        #pragma unroll
        for (int j = ty; j < 32; j += 4)
            tile[j][tx] = src[(size_t)j * N + tx];
        __syncthreads();

        int cx = threadIdx.x & 31;
        int cy = threadIdx.x >> 5;
        float* dst = g_featT + ((size_t)b * N + nb * 128) * F + fb * 32;
        #pragma unroll
        for (int j = cy; j < 128; j += 16)
            dst[(size_t)j * F + cx] = tile[cx][j];
    }
}

// ---------------- feature propagation: 1024 thr, 2 warps per query ---------
__global__ __launch_bounds__(1024) void feat_kernel(float* __restrict__ out)
{
    __shared__ float so[16][260];

    const int lane   = threadIdx.x & 31;
    const int wid    = threadIdx.x >> 5;       // 0..31
    const int qlocal = wid >> 1;               // 0..15
    const int half   = wid & 1;                // 0/1 -> 128 features each
    const int b      = blockIdx.x >> 7;        // 128 blocks per batch
    const int m0     = (blockIdx.x & 127) * 16;
    const int m      = m0 + qlocal;
    const size_t gq  = (size_t)b * M + m;

    int   iv = 0;
    float wv = 0.0f;
    if (lane < K) {
        iv = g_idx[gq * K + lane];
        wv = g_w[gq * K + lane];
    }

    float4 acc = make_float4(0.f, 0.f, 0.f, 0.f);
    #pragma unroll
    for (int j = 0; j < K; ++j) {
        float wj = __shfl_sync(FULL, wv, j);
        int   ij = __shfl_sync(FULL, iv, j);
        const float4* base =
            (const float4*)(g_featT + ((size_t)b * N + ij) * F + half * 128);
        float4 u = base[lane];
        acc.x = fmaf(wj, u.x, acc.x);
        acc.y = fmaf(wj, u.y, acc.y);
        acc.z = fmaf(wj, u.z, acc.z);
        acc.w = fmaf(wj, u.w, acc.w);
    }

    *(float4*)&so[qlocal][half * 128 + 4 * lane] = acc;
    __syncthreads();

    // warp wid writes f rows [wid*8, wid*8+8); lanes: 2 f x 16 mLocal
    #pragma unroll
    for (int r = 0; r < 4; ++r) {
        int f  = wid * 8 + r * 2 + (lane >> 4);
        int ml = lane & 15;
        out[((size_t)b * OUTC + 3 + f) * M + m0 + ml] = so[ml][f];
    }
}

// ---------------------------------------------------------------------------
extern "C" void kernel_launch(void* const* d_in, const int* in_sizes, int n_in,
                              void* d_out, int out_size)
{
    const float* pc   = (const float*)d_in[0];  // point_cloud (B,3,N)
    const float* qc   = (const float*)d_in[1];  // query_cloud (B,3,M)
    const float* feat = (const float*)d_in[2];  // point_features (B,F,N)
    const float* temp = (const float*)d_in[3];  // temperature scalar
    float* out = (float*)d_out;

    zero_kernel<<<1, 512>>>();
    hist_kernel<<<(B * N + B * M) / 512, 512>>>(pc, qc);
    scan_kernel<<<1, 256>>>();
    scatter_kernel<<<(B * N + B * M) / 512, 512>>>(pc, qc);
    bounds_kernel<<<(B * NG + 511) / 512, 512>>>();
    envelope_kernel<<<1, 256>>>();
    knn_tr_kernel<<<KNNB + TRB, 512>>>(qc, temp, feat, out);
    feat_kernel<<<(B * M) / 16, 1024>>>(out);
}

// round 11
// speedup vs baseline: 2.1001x; 2.1001x over previous
#include <cuda_runtime.h>
#include <cuda_bf16.h>
#include <float.h>

#define FULL 0xFFFFFFFFu

static constexpr int B = 4;
static constexpr int N = 8192;
static constexpr int M = 2048;
static constexpr int F = 256;
static constexpr int K = 16;
static constexpr int OUTC = 3 + F;  // 259

static constexpr int KNNB = (B * M) / 16;              // 512 knn blocks
static constexpr int TRB  = B * (F / 32) * (N / 128);  // 2048 transpose tiles

// Scratch (device globals — no allocation allowed)
__device__ float g_featT[(size_t)B * N * F];   // 32MB transposed features (B,N,F)
__device__ int   g_idx[(size_t)B * M * K];
__device__ float g_w[(size_t)B * M * K];

// ---------------------------------------------------------------------------
// Fused kernel, 512-thread blocks.
//   blocks [0, 512):     KNN — R1-exact selection (warp per query, all 8192
//                        points in original order, key s = |p|^2 - 2 q.p).
//                        Pairwise tile screening: one ballot on min(sa,sb)
//                        gates the exact per-tile ballots. Bit-identical
//                        selection (screen-miss => both tile ballots empty;
//                        thr only tightens).
//   blocks [512, 2560):  feature transpose (B,F,N)->(B,N,F), co-resident
//                        DRAM streaming overlapped with the smem-bound KNN.
// ---------------------------------------------------------------------------
__global__ __launch_bounds__(512) void fused_knn_transpose(
    const float* __restrict__ pc,     // (B,3,N)
    const float* __restrict__ qc,     // (B,3,M)
    const float* __restrict__ temperature,
    const float* __restrict__ feat,   // (B,F,N)
    float* __restrict__ out)          // (B,259,M)
{
    __shared__ __align__(16) unsigned char smem_raw[32768];

    if (blockIdx.x < KNNB) {
        // ===================== KNN =====================
        float4* s_pts = (float4*)smem_raw;    // 2048 * 16B = 32KB

        const int tid  = threadIdx.x;
        const int lane = tid & 31;
        const int wid  = tid >> 5;
        const int b    = blockIdx.x >> 7;              // 128 blocks per batch
        const int m    = ((blockIdx.x & 127) << 4) + wid;

        const float* pcb = pc + (size_t)b * 3 * N;

        const float qx = qc[((size_t)b * 3 + 0) * M + m];
        const float qy = qc[((size_t)b * 3 + 1) * M + m];
        const float qz = qc[((size_t)b * 3 + 2) * M + m];
        const float ax = -2.0f * qx, ay = -2.0f * qy, az = -2.0f * qz;

        float kd = FLT_MAX;   // warp-sorted list: lane i = i-th smallest
        int   ki = 0;
        float thr = FLT_MAX;  // lazy copy of element 15 (16th smallest)

        // exact per-tile insert (identical to R1's)
        auto insert_tile = [&](float s, int nbase) {
            unsigned mask = __ballot_sync(FULL, s < thr);
            if (mask) {
                do {
                    int src = __ffs(mask) - 1;
                    mask &= mask - 1;
                    float cd = __shfl_sync(FULL, s, src);
                    int   cn = nbase + src;
                    int pos = __popc(__ballot_sync(FULL, kd < cd));
                    float ud = __shfl_up_sync(FULL, kd, 1);
                    int   ui = __shfl_up_sync(FULL, ki, 1);
                    if (lane >= pos) {
                        kd = (lane == pos) ? cd : ud;
                        ki = (lane == pos) ? cn : ui;
                    }
                } while (mask);
                thr = __shfl_sync(FULL, kd, 15);
            }
        };

        for (int c = 0; c < 4; ++c) {
            __syncthreads();
            for (int i = tid; i < 2048; i += 512) {
                int n = c * 2048 + i;
                float x = pcb[n];
                float y = pcb[N + n];
                float z = pcb[2 * N + n];
                s_pts[i] = make_float4(x, y, z, fmaf(x, x, fmaf(y, y, z * z)));
            }
            __syncthreads();

            #pragma unroll 4
            for (int t = 0; t < 64; t += 2) {
                float4 pa = s_pts[t * 32 + lane];
                float4 pb = s_pts[t * 32 + 32 + lane];
                float sa = fmaf(ax, pa.x, pa.w);
                sa = fmaf(ay, pa.y, sa);
                sa = fmaf(az, pa.z, sa);
                float sb = fmaf(ax, pb.x, pb.w);
                sb = fmaf(ay, pb.y, sb);
                sb = fmaf(az, pb.z, sb);
                // one screening ballot for both tiles (thr only tightens, so
                // screen-miss implies both exact tile ballots would be empty)
                if (__ballot_sync(FULL, fminf(sa, sb) < thr)) {
                    int nbase = c * 2048 + t * 32;
                    insert_tile(sa, nbase);        // tile t   (original order)
                    insert_tile(sb, nbase + 32);   // tile t+1 (uses updated thr)
                }
            }
        }

        // softmax over the 16 smallest (shift-invariant in s)
        float tv = *temperature;
        float sigma = fmaxf(tv * tv, 1e-4f);
        float inv_sigma = 1.0f / sigma;
        float s0 = __shfl_sync(FULL, kd, 0);
        float ev = (lane < K) ? __expf((s0 - kd) * inv_sigma) : 0.0f;
        float sum = ev;
        #pragma unroll
        for (int o = 16; o; o >>= 1) sum += __shfl_xor_sync(FULL, sum, o);
        float w = ev / sum;

        // projected points: sum_k w_k * p_k (lanes >= 16 contribute w = 0)
        float px = pcb[ki];
        float py = pcb[N + ki];
        float pz = pcb[2 * N + ki];
        float sx = w * px, sy = w * py, sz = w * pz;
        #pragma unroll
        for (int o = 16; o; o >>= 1) {
            sx += __shfl_xor_sync(FULL, sx, o);
            sy += __shfl_xor_sync(FULL, sy, o);
            sz += __shfl_xor_sync(FULL, sz, o);
        }
        if (lane == 0) {
            out[((size_t)b * OUTC + 0) * M + m] = sx;
            out[((size_t)b * OUTC + 1) * M + m] = sy;
            out[((size_t)b * OUTC + 2) * M + m] = sz;
        }
        if (lane < K) {
            size_t gq = (size_t)b * M + m;
            g_idx[gq * K + lane] = ki;
            g_w[gq * K + lane]   = w;
        }
    } else {
        // ===================== transpose ==============
        // (B,F,N) -> (B,N,F); tile = 32 f x 128 n per block
        float (*tile)[129] = (float (*)[129])smem_raw;   // 32*129*4 = 16512B

        int t  = blockIdx.x - KNNB;         // 0..2047
        int b  = t >> 9;                    // 512 tiles per batch
        int r  = t & 511;
        int fb = r >> 6;                    // 0..7  (f block of 32)
        int nb = r & 63;                    // 0..63 (n block of 128)

        int tx = threadIdx.x & 127;         // n within tile
        int ty = threadIdx.x >> 7;          // 0..3
        const float* src = feat + ((size_t)b * F + fb * 32) * N + nb * 128;
        #pragma unroll
        for (int j = ty; j < 32; j += 4)
            tile[j][tx] = src[(size_t)j * N + tx];
        __syncthreads();

        int cx = threadIdx.x & 31;          // f within tile
        int cy = threadIdx.x >> 5;          // 0..15
        float* dst = g_featT + ((size_t)b * N + nb * 128) * F + fb * 32;
        #pragma unroll
        for (int j = cy; j < 128; j += 16)
            dst[(size_t)j * F + cx] = tile[cx][j];
    }
}

// ---------------------------------------------------------------------------
// Feature propagation: 1024 threads = 32 warps = 16 queries, 2 warps/query
// (each warp gathers 128 of the 256 features -> 2x memory-level parallelism
// on this latency-bound gather). Ran correct in R10.
// ---------------------------------------------------------------------------
__global__ __launch_bounds__(1024) void feat_kernel(float* __restrict__ out)
{
    __shared__ float so[16][260];

    const int lane   = threadIdx.x & 31;
    const int wid    = threadIdx.x >> 5;       // 0..31
    const int qlocal = wid >> 1;               // 0..15
    const int half   = wid & 1;                // 0/1 -> 128 features each
    const int b      = blockIdx.x >> 7;        // 128 blocks per batch
    const int m0     = (blockIdx.x & 127) * 16;
    const int m      = m0 + qlocal;
    const size_t gq  = (size_t)b * M + m;

    int   iv = 0;
    float wv = 0.0f;
    if (lane < K) {
        iv = g_idx[gq * K + lane];
        wv = g_w[gq * K + lane];
    }

    float4 acc = make_float4(0.f, 0.f, 0.f, 0.f);
    #pragma unroll
    for (int j = 0; j < K; ++j) {
        float wj = __shfl_sync(FULL, wv, j);
        int   ij = __shfl_sync(FULL, iv, j);
        const float4* base =
            (const float4*)(g_featT + ((size_t)b * N + ij) * F + half * 128);
        float4 u = base[lane];
        acc.x = fmaf(wj, u.x, acc.x);
        acc.y = fmaf(wj, u.y, acc.y);
        acc.z = fmaf(wj, u.z, acc.z);
        acc.w = fmaf(wj, u.w, acc.w);
    }

    *(float4*)&so[qlocal][half * 128 + 4 * lane] = acc;
    __syncthreads();

    // warp wid writes f rows [wid*8, wid*8+8); lanes: 2 f x 16 mLocal
    #pragma unroll
    for (int r = 0; r < 4; ++r) {
        int f  = wid * 8 + r * 2 + (lane >> 4);
        int ml = lane & 15;
        out[((size_t)b * OUTC + 3 + f) * M + m0 + ml] = so[ml][f];
    }
}

// ---------------------------------------------------------------------------
extern "C" void kernel_launch(void* const* d_in, const int* in_sizes, int n_in,
                              void* d_out, int out_size)
{
    const float* pc   = (const float*)d_in[0];  // point_cloud (B,3,N)
    const float* qc   = (const float*)d_in[1];  // query_cloud (B,3,M)
    const float* feat = (const float*)d_in[2];  // point_features (B,F,N)
    const float* temp = (const float*)d_in[3];  // temperature scalar
    float* out = (float*)d_out;

    fused_knn_transpose<<<KNNB + TRB, 512>>>(pc, qc, temp, feat, out);
    feat_kernel<<<(B * M) / 16, 1024>>>(out);
}